// round 4
// baseline (speedup 1.0000x reference)
#include <cuda_runtime.h>
#include <cuda_bf16.h>
#include <cstdint>

// R4: R3's L2-residency plan, with hints on 256-bit loads (sm_100 ptxas
// requires .v8.b32 for L2::evict_* on ld).
//
//   pinned  (evict_last):  dir (32 MB) + first 32 MB of z1 + first 32 MB of z2
//   stream  (evict_first): remaining ~112 MB of z1/z2
//   output  (st.cs):       never re-read; don't occupy L2
//
// All staging is 32B-granular and exactly aligned:
//   z block chunk: 256 rows * 44 B = 11264 B = 352 x 32 B
//   dir block chunk: 256 rows * 16 B = 4096 B = 128 x 32 B
//   totals divisible by 32 B (2e6*44 and 2e6*16).
// z_3 remains unread (reference discards c_3).

constexpr int TPB  = 256;
constexpr int ROWS = 256;
constexpr int WORDS_PER_BLOCK = ROWS * 11;            // 2816 floats per z array
constexpr int F8_PER_BLOCK    = WORDS_PER_BLOCK / 8;  // 352 (32B units)
constexpr int D8_PER_BLOCK    = ROWS * 4 / 8;         // 128 (32B units of dir)

// 32 MB prefix of each z array pinned in L2 (in 32B units).
constexpr long PIN_F8 = (32L * 1024 * 1024) / 32;     // 1,048,576

__device__ __forceinline__ void ldg256_last(const void* p, uint4& a, uint4& b) {
    asm("ld.global.nc.L2::evict_last.v8.b32 {%0,%1,%2,%3,%4,%5,%6,%7}, [%8];"
        : "=r"(a.x), "=r"(a.y), "=r"(a.z), "=r"(a.w),
          "=r"(b.x), "=r"(b.y), "=r"(b.z), "=r"(b.w)
        : "l"(p));
}
__device__ __forceinline__ void ldg256_first(const void* p, uint4& a, uint4& b) {
    asm("ld.global.nc.L2::evict_first.v8.b32 {%0,%1,%2,%3,%4,%5,%6,%7}, [%8];"
        : "=r"(a.x), "=r"(a.y), "=r"(a.z), "=r"(a.w),
          "=r"(b.x), "=r"(b.y), "=r"(b.z), "=r"(b.w)
        : "l"(p));
}
__device__ __forceinline__ void stg_f32_cs(float* p, float v) {
    asm volatile("st.global.cs.f32 [%0], %1;" :: "l"(p), "f"(v) : "memory");
}

__global__ __launch_bounds__(TPB)
void yolo_zone_kernel(const char* __restrict__ z1b,
                      const char* __restrict__ z2b,
                      const char* __restrict__ dirb,
                      float* __restrict__ out,
                      int n, long nf8, long nd8)
{
    __shared__ float s1[WORDS_PER_BLOCK];
    __shared__ float s2[WORDS_PER_BLOCK];
    __shared__ float sdir[ROWS * 4];

    const int t = threadIdx.x;

    // ---- stage z1/z2 (352 x 32B each; iterations k=0 full, k=1 partial) ----
    const long baseZ = (long)blockIdx.x * F8_PER_BLOCK;
    #pragma unroll
    for (int k = 0; k < 2; k++) {
        int  sidx = t + k * TPB;
        long g    = baseZ + sidx;
        if (sidx < F8_PER_BLOCK && g < nf8) {
            uint4 a, b, c, d;
            if (g < PIN_F8) {
                ldg256_last(z1b + g * 32, a, b);
                ldg256_last(z2b + g * 32, c, d);
            } else {
                ldg256_first(z1b + g * 32, a, b);
                ldg256_first(z2b + g * 32, c, d);
            }
            reinterpret_cast<uint4*>(s1)[2 * sidx]     = a;
            reinterpret_cast<uint4*>(s1)[2 * sidx + 1] = b;
            reinterpret_cast<uint4*>(s2)[2 * sidx]     = c;
            reinterpret_cast<uint4*>(s2)[2 * sidx + 1] = d;
        }
    }

    // ---- stage dir (128 x 32B, always pinned) ----
    {
        long gd = (long)blockIdx.x * D8_PER_BLOCK + t;
        if (t < D8_PER_BLOCK && gd < nd8) {
            uint4 a, b;
            ldg256_last(dirb + gd * 32, a, b);
            reinterpret_cast<uint4*>(sdir)[2 * t]     = a;
            reinterpret_cast<uint4*>(sdir)[2 * t + 1] = b;
        }
    }

    __syncthreads();

    const int row = blockIdx.x * ROWS + t;
    if (row >= n) return;

    const int w = t * 11;
    float a0 = s1[w + 0], a1 = s1[w + 1], a2 = s1[w + 2], a3 = s1[w + 3];
    float b0 = s2[w + 0], b1 = s2[w + 1], b2 = s2[w + 2], b3 = s2[w + 3];
    float4 d = reinterpret_cast<const float4*>(sdir)[t];

    // Centers and direction vector (division by 2 exact in fp32).
    float dx = (b0 + b2) * 0.5f - (a0 + a2) * 0.5f;
    float dy = -((b1 + b3) * 0.5f - (a1 + a3) * 0.5f);

    // degrees(atan2), truncate toward zero (matches .astype(int32)).
    float phi = atan2f(dy, dx) * 57.29577951308232f;
    int phi_long = (int)phi;

    // python-style mod 360 of (90 - phi_long); range [-90, 270] -> one fixup.
    int m = 90 - phi_long;
    if (m < 0) m += 360;
    if (m >= 360) m -= 360;

    // zone = floor((m + 45) / 90) mod 4
    int zone = ((m + 45) / 90) & 3;

    float r = (zone == 0) ? d.x : (zone == 1) ? d.y : (zone == 2) ? d.z : d.w;
    stg_f32_cs(out + row, r);
}

extern "C" void kernel_launch(void* const* d_in, const int* in_sizes, int n_in,
                              void* d_out, int out_size)
{
    const char* z1b  = (const char*)d_in[0];
    const char* z2b  = (const char*)d_in[1];
    // d_in[2] (z_3) intentionally unused — reference discards c_3.
    const char* dirb = (const char*)d_in[3];
    float*      out  = (float*)d_out;

    int  n   = out_size;
    long nf8 = ((long)n * 11 * 4) / 32;   // 32B units per z array (exact)
    long nd8 = ((long)n * 16) / 32;       // 32B units of dir (exact)

    int grid = (n + ROWS - 1) / ROWS;
    yolo_zone_kernel<<<grid, TPB>>>(z1b, z2b, dirb, out, n, nf8, nd8);
}